// round 1
// baseline (speedup 1.0000x reference)
#include <cuda_runtime.h>
#include <math.h>

#define MAXT 4096
#define KTOT 928      // 160 (padded features) + 768 backbone
#define K1   160
#define D_BB 768

// Device scratch (no dynamic allocation allowed)
__device__ float  g_feat[MAXT * K1];       // padded outer-product features
__device__ float2 g_scal[MAXT];            // (mean_enode, sum_ccl*sum_cnd)
__device__ float  g_w1r[KTOT * 128];       // repacked W1: rows 150..159 = 0

// ---------------------------------------------------------------------------
// Prep 1: repack W1 [918,128] -> [928,128] with zero rows 150..159
// ---------------------------------------------------------------------------
__global__ void prep_w(const float* __restrict__ W1) {
    int idx = blockIdx.x * blockDim.x + threadIdx.x;
    if (idx >= KTOT * 128) return;
    int row = idx >> 7;
    int col = idx & 127;
    float v;
    if (row < 150)       v = W1[row * 128 + col];
    else if (row < 160)  v = 0.0f;
    else                 v = W1[(row - 10) * 128 + col];
    g_w1r[idx] = v;
}

// ---------------------------------------------------------------------------
// Prep 2: per-task features (5x5x6 outer product) + scalar reductions
// One warp per task.
// ---------------------------------------------------------------------------
__global__ void prep_feat(const float* __restrict__ res,
                          const float* __restrict__ fr,
                          const float* __restrict__ estep,
                          const float* __restrict__ enode,
                          const float* __restrict__ ccl,
                          const float* __restrict__ cnd,
                          int T) {
    int warp = (blockIdx.x * blockDim.x + threadIdx.x) >> 5;
    int lane = threadIdx.x & 31;
    if (warp >= T) return;
    int t = warp;
    const float* r = res   + t * 5;
    const float* f = fr    + t * 5;
    const float* e = estep + t * 6;

    #pragma unroll
    for (int it = 0; it < 5; it++) {
        int idx = lane + it * 32;            // 0..159
        float v = 0.0f;
        if (idx < 150) {
            int n   = idx / 30;
            int rem = idx - n * 30;
            int m   = rem / 6;
            int o   = rem - m * 6;
            v = r[n] * f[m] * e[o];
        }
        g_feat[t * K1 + idx] = v;
    }

    float se = enode[t * 64 + lane] + enode[t * 64 + lane + 32];
    float sc = (lane < 4) ? ccl[t * 4 + lane] : 0.0f;
    float sn = cnd[t * 32 + lane];
    #pragma unroll
    for (int off = 16; off; off >>= 1) {
        se += __shfl_xor_sync(0xffffffffu, se, off);
        sc += __shfl_xor_sync(0xffffffffu, sc, off);
        sn += __shfl_xor_sync(0xffffffffu, sn, off);
    }
    if (lane == 0) g_scal[t] = make_float2(se * (1.0f / 64.0f), sc * sn);
}

// ---------------------------------------------------------------------------
// Main: fused GEMM [T,928]x[928,128] + relu + 4 dot products + final combine.
// Block: 256 threads, M_TILE=32 tasks, full N=128.
// Thread (lane,warp) computes 4x4 register tile: rows warp*4.., cols lane*4..
// ---------------------------------------------------------------------------
__global__ void __launch_bounds__(256)
critic_main(const float* __restrict__ bb,
            const float* __restrict__ b1,
            const float* __restrict__ W3, const float* __restrict__ b3,
            const float* __restrict__ W4, const float* __restrict__ b4,
            const float* __restrict__ W5, const float* __restrict__ b5,
            const float* __restrict__ W6, const float* __restrict__ b6,
            float* __restrict__ out, int T) {
    __shared__ float Xs[8][33];    // [kk][m], padded
    __shared__ float Ws[8][128];   // [kk][n]

    const int tid  = threadIdx.x;
    const int lane = tid & 31;
    const int wid  = tid >> 5;
    const int n0   = lane * 4;
    const int m0   = wid * 4;
    const int mbase = blockIdx.x * 32;

    // X loader mapping: 256 threads -> 32 rows x 8 k
    const int lkk = tid & 7;
    const int lm  = tid >> 3;
    const int ltask = mbase + lm;
    const bool lvalid = (ltask < T);
    const float* featrow = g_feat + (size_t)(lvalid ? ltask : 0) * K1;
    const float* bbrow   = bb     + (size_t)(lvalid ? ltask : 0) * D_BB;

    // W loader mapping: kk = tid>>5 (0..7), 4 cols starting at (tid&31)*4
    const int wkk = tid >> 5;
    const int wc  = (tid & 31) * 4;

    float acc[4][4] = {{0.f,0.f,0.f,0.f},{0.f,0.f,0.f,0.f},
                       {0.f,0.f,0.f,0.f},{0.f,0.f,0.f,0.f}};

    for (int c = 0; c < KTOT / 8; c++) {
        int k0 = c * 8;
        float xv = 0.0f;
        if (lvalid)
            xv = (k0 < K1) ? featrow[k0 + lkk] : bbrow[k0 - K1 + lkk];
        float4 wv = *(const float4*)&g_w1r[(k0 + wkk) * 128 + wc];

        __syncthreads();
        Xs[lkk][lm] = xv;
        *(float4*)&Ws[wkk][wc] = wv;
        __syncthreads();

        #pragma unroll
        for (int kk = 0; kk < 8; kk++) {
            float4 w = *(const float4*)&Ws[kk][n0];
            float x0 = Xs[kk][m0 + 0];
            float x1 = Xs[kk][m0 + 1];
            float x2 = Xs[kk][m0 + 2];
            float x3 = Xs[kk][m0 + 3];
            acc[0][0] = fmaf(x0, w.x, acc[0][0]);
            acc[0][1] = fmaf(x0, w.y, acc[0][1]);
            acc[0][2] = fmaf(x0, w.z, acc[0][2]);
            acc[0][3] = fmaf(x0, w.w, acc[0][3]);
            acc[1][0] = fmaf(x1, w.x, acc[1][0]);
            acc[1][1] = fmaf(x1, w.y, acc[1][1]);
            acc[1][2] = fmaf(x1, w.z, acc[1][2]);
            acc[1][3] = fmaf(x1, w.w, acc[1][3]);
            acc[2][0] = fmaf(x2, w.x, acc[2][0]);
            acc[2][1] = fmaf(x2, w.y, acc[2][1]);
            acc[2][2] = fmaf(x2, w.z, acc[2][2]);
            acc[2][3] = fmaf(x2, w.w, acc[2][3]);
            acc[3][0] = fmaf(x3, w.x, acc[3][0]);
            acc[3][1] = fmaf(x3, w.y, acc[3][1]);
            acc[3][2] = fmaf(x3, w.z, acc[3][2]);
            acc[3][3] = fmaf(x3, w.w, acc[3][3]);
        }
    }

    // Epilogue: bias + relu + partial dots with W3..W6 over this thread's cols
    float bj[4], w3[4], w4[4], w5[4], w6[4];
    #pragma unroll
    for (int j = 0; j < 4; j++) {
        bj[j] = b1[n0 + j];
        w3[j] = W3[n0 + j];
        w4[j] = W4[n0 + j];
        w5[j] = W5[n0 + j];
        w6[j] = W6[n0 + j];
    }
    float p3[4] = {0,0,0,0}, p4[4] = {0,0,0,0}, p5[4] = {0,0,0,0}, p6[4] = {0,0,0,0};
    #pragma unroll
    for (int i = 0; i < 4; i++) {
        #pragma unroll
        for (int j = 0; j < 4; j++) {
            float h = fmaxf(acc[i][j] + bj[j], 0.0f);
            p3[i] = fmaf(h, w3[j], p3[i]);
            p4[i] = fmaf(h, w4[j], p4[i]);
            p5[i] = fmaf(h, w5[j], p5[i]);
            p6[i] = fmaf(h, w6[j], p6[i]);
        }
    }
    // full warp butterfly reductions (every lane ends with the totals)
    #pragma unroll
    for (int off = 16; off; off >>= 1) {
        #pragma unroll
        for (int i = 0; i < 4; i++) {
            p3[i] += __shfl_xor_sync(0xffffffffu, p3[i], off);
            p4[i] += __shfl_xor_sync(0xffffffffu, p4[i], off);
            p5[i] += __shfl_xor_sync(0xffffffffu, p5[i], off);
            p6[i] += __shfl_xor_sync(0xffffffffu, p6[i], off);
        }
    }

    if (lane < 4) {
        int i = lane;
        int task = mbase + m0 + i;
        if (task < T) {
            float2 sc = g_scal[task];
            float me = sc.x;   // mean(enode)
            float se = sc.y;   // sum(ccl)*sum(cnd)
            float y51 = 1.0f / (1.0f + expf(-(p3[i] * me + b3[0])));
            float y61 = p4[i] * me + b4[0];
            float y52 = 1.0f / (1.0f + expf(-(p5[i] * se + b5[0])));
            float y62 = p6[i] * se + b6[0];
            float p = y51 * y52;
            out[task] = (1.0f - p) * (-100.0f) + p * (y61 + y62);
        }
    }
}

// ---------------------------------------------------------------------------
extern "C" void kernel_launch(void* const* d_in, const int* in_sizes, int n_in,
                              void* d_out, int out_size) {
    const float* bb    = (const float*)d_in[2];
    const float* res   = (const float*)d_in[3];
    const float* fr    = (const float*)d_in[4];
    const float* estep = (const float*)d_in[5];
    const float* enode = (const float*)d_in[6];
    const float* ccl   = (const float*)d_in[7];
    const float* cnd   = (const float*)d_in[8];
    const float* W1    = (const float*)d_in[9];
    const float* b1    = (const float*)d_in[10];
    const float* W3    = (const float*)d_in[11];
    const float* b3    = (const float*)d_in[12];
    const float* W4    = (const float*)d_in[13];
    const float* b4    = (const float*)d_in[14];
    const float* W5    = (const float*)d_in[15];
    const float* b5    = (const float*)d_in[16];
    const float* W6    = (const float*)d_in[17];
    const float* b6    = (const float*)d_in[18];

    int T = in_sizes[2] / D_BB;
    if (T > MAXT) T = MAXT;

    prep_w<<<(KTOT * 128 + 255) / 256, 256>>>(W1);
    prep_feat<<<(T + 7) / 8, 256>>>(res, fr, estep, enode, ccl, cnd, T);
    critic_main<<<(T + 31) / 32, 256>>>(bb, b1, W3, b3, W4, b4, W5, b5, W6, b6,
                                        (float*)d_out, T);
}

// round 2
// speedup vs baseline: 1.4015x; 1.4015x over previous
#include <cuda_runtime.h>
#include <math.h>

#define D_BB 768
#define K1   160      // padded outer-product features (150 real + 10 zero)
#define KTOT 928      // K1 + D_BB
#define NCH  58       // KTOT / 16

typedef unsigned long long u64;

// ---- packed f32x2 helpers (FFMA2 path: only reachable via PTX) -------------
__device__ __forceinline__ u64 dup2(float v) {
    u64 r;
    asm("mov.b64 %0, {%1, %1};" : "=l"(r) : "f"(v));
    return r;
}
__device__ __forceinline__ void fma2(u64 &d, u64 a, u64 b) {
    asm("fma.rn.f32x2 %0, %1, %2, %0;" : "+l"(d) : "l"(a), "l"(b));
}
__device__ __forceinline__ float2 unpack2(u64 v) {
    float lo, hi;
    asm("mov.b64 {%0, %1}, %2;" : "=f"(lo), "=f"(hi) : "l"(v));
    return make_float2(lo, hi);
}

// ---------------------------------------------------------------------------
// Single fused kernel.
// Block: 256 threads, 32 tasks (M), full N=128.
// Thread (wid, lane): rows wid*4..+3 (as 2 packed pairs), cols lane*4..+3.
// K pipeline: chunks of 16; k<160 reads per-block feature tile in shared,
// k>=160 stages backbone through Xs. W1 row-remap (918->928) done inline.
// ---------------------------------------------------------------------------
__global__ void __launch_bounds__(256)
critic_fused(const float* __restrict__ bb,
             const float* __restrict__ res,   const float* __restrict__ fr,
             const float* __restrict__ estep, const float* __restrict__ enode,
             const float* __restrict__ ccl,   const float* __restrict__ cnd,
             const float* __restrict__ W1,    const float* __restrict__ b1,
             const float* __restrict__ W3,    const float* __restrict__ b3,
             const float* __restrict__ W4,    const float* __restrict__ b4,
             const float* __restrict__ W5,    const float* __restrict__ b5,
             const float* __restrict__ W6,    const float* __restrict__ b6,
             float* __restrict__ out, int T)
{
    __shared__ __align__(16) float  featT[K1][32];   // [k][m], m contiguous
    __shared__ __align__(16) float  Xs[16][34];      // [kk][m], stride 34 (8B-aligned rows)
    __shared__ __align__(16) float  Ws[16][128];     // [kk][n]
    __shared__ float2 scalS[32];                     // (mean enode, sum ccl * sum cnd)

    const int tid   = threadIdx.x;
    const int lane  = tid & 31;
    const int wid   = tid >> 5;
    const int mbase = blockIdx.x * 32;
    const int n0    = lane * 4;
    const int m0    = wid * 4;

    // ---- per-task scalar reductions: 8 warps x 4 tasks ----
    #pragma unroll
    for (int st = 0; st < 4; st++) {
        int m = wid * 4 + st;
        int task = mbase + m; if (task >= T) task = T - 1;
        float se = enode[(size_t)task * 64 + lane] + enode[(size_t)task * 64 + lane + 32];
        float sc = (lane < 4) ? ccl[task * 4 + lane] : 0.0f;
        float sn = cnd[(size_t)task * 32 + lane];
        #pragma unroll
        for (int off = 16; off; off >>= 1) {
            se += __shfl_xor_sync(0xffffffffu, se, off);
            sc += __shfl_xor_sync(0xffffffffu, sc, off);
            sn += __shfl_xor_sync(0xffffffffu, sn, off);
        }
        if (lane == 0) scalS[m] = make_float2(se * (1.0f / 64.0f), sc * sn);
    }

    // ---- 5x5x6 outer-product features into featT (idx-major -> conflict-free) ----
    for (int i = tid; i < 32 * K1; i += 256) {
        int m = i & 31;
        int idx = i >> 5;
        int task = mbase + m; if (task >= T) task = T - 1;
        float v = 0.0f;
        if (idx < 150) {
            int n = idx / 30, rem = idx - n * 30;
            int mm = rem / 6, o = rem - mm * 6;
            v = res[task * 5 + n] * fr[task * 5 + mm] * estep[task * 6 + o];
        }
        featT[idx][m] = v;
    }

    // ---- loader mappings ----
    const int wkk = tid >> 4;            // 0..15 (W k-row within chunk)
    const int wc  = (tid & 15) * 8;      // 8 floats per thread
    const int lkk = tid & 15;            // Xs k within chunk
    const int lm  = tid >> 4;            // Xs row (0..15); also handles row+16
    int xt0 = mbase + lm;      if (xt0 >= T) xt0 = T - 1;
    int xt1 = mbase + lm + 16; if (xt1 >= T) xt1 = T - 1;
    const float* bb0 = bb + (size_t)xt0 * D_BB + lkk;
    const float* bb1 = bb + (size_t)xt1 * D_BB + lkk;

    u64 acc[2][4];
    #pragma unroll
    for (int p = 0; p < 2; p++)
        #pragma unroll
        for (int j = 0; j < 4; j++) acc[p][j] = 0ull;

    // W1 row remap loader (rows 150..159 are zero pad)
    auto load_w = [&](int c, float4 &a, float4 &b) {
        int row = c * 16 + wkk;
        a = make_float4(0.f, 0.f, 0.f, 0.f);
        b = a;
        int sr = (row < 160) ? row : row - 10;
        if (row < 150 || row >= 160) {
            const float* p = W1 + (size_t)sr * 128 + wc;
            a = *(const float4*)p;
            b = *(const float4*)(p + 4);
        }
    };

    // preload chunk 0
    float4 wa, wb;
    load_w(0, wa, wb);
    float x0 = 0.0f, x1 = 0.0f;

    for (int c = 0; c < NCH; c++) {
        const int k0 = c * 16;

        __syncthreads();                       // prev compute done (also fences featT/scalS at c=0)
        *(float4*)&Ws[wkk][wc]     = wa;
        *(float4*)&Ws[wkk][wc + 4] = wb;
        if (k0 >= K1) {
            Xs[lkk][lm]      = x0;
            Xs[lkk][lm + 16] = x1;
        }
        __syncthreads();

        // preload next chunk while computing this one (hide LDG latency)
        if (c + 1 < NCH) {
            load_w(c + 1, wa, wb);
            int kb = (c + 1) * 16 - K1;
            if (kb >= 0) { x0 = bb0[kb]; x1 = bb1[kb]; }
        }

        if (k0 < K1) {
            const float* xp = &featT[k0][0];
            #pragma unroll
            for (int kk = 0; kk < 16; kk++) {
                u64 xa = *(const u64*)(xp + kk * 32 + m0);
                u64 xb = *(const u64*)(xp + kk * 32 + m0 + 2);
                float4 w = *(const float4*)&Ws[kk][n0];
                u64 w0 = dup2(w.x), w1 = dup2(w.y), w2 = dup2(w.z), w3 = dup2(w.w);
                fma2(acc[0][0], xa, w0); fma2(acc[0][1], xa, w1);
                fma2(acc[0][2], xa, w2); fma2(acc[0][3], xa, w3);
                fma2(acc[1][0], xb, w0); fma2(acc[1][1], xb, w1);
                fma2(acc[1][2], xb, w2); fma2(acc[1][3], xb, w3);
            }
        } else {
            #pragma unroll
            for (int kk = 0; kk < 16; kk++) {
                u64 xa = *(const u64*)(&Xs[kk][m0]);
                u64 xb = *(const u64*)(&Xs[kk][m0 + 2]);
                float4 w = *(const float4*)&Ws[kk][n0];
                u64 w0 = dup2(w.x), w1 = dup2(w.y), w2 = dup2(w.z), w3 = dup2(w.w);
                fma2(acc[0][0], xa, w0); fma2(acc[0][1], xa, w1);
                fma2(acc[0][2], xa, w2); fma2(acc[0][3], xa, w3);
                fma2(acc[1][0], xb, w0); fma2(acc[1][1], xb, w1);
                fma2(acc[1][2], xb, w2); fma2(acc[1][3], xb, w3);
            }
        }
    }

    // ---- epilogue: unpack, bias+relu, 4 dot products, combine ----
    float hv[4][4];
    #pragma unroll
    for (int j = 0; j < 4; j++) {
        float2 lo = unpack2(acc[0][j]);   // rows m0, m0+1
        float2 hi = unpack2(acc[1][j]);   // rows m0+2, m0+3
        hv[0][j] = lo.x; hv[1][j] = lo.y; hv[2][j] = hi.x; hv[3][j] = hi.y;
    }

    float bj[4], w3v[4], w4v[4], w5v[4], w6v[4];
    #pragma unroll
    for (int j = 0; j < 4; j++) {
        bj[j]  = b1[n0 + j];
        w3v[j] = W3[n0 + j];
        w4v[j] = W4[n0 + j];
        w5v[j] = W5[n0 + j];
        w6v[j] = W6[n0 + j];
    }
    float p3[4] = {0,0,0,0}, p4[4] = {0,0,0,0}, p5[4] = {0,0,0,0}, p6[4] = {0,0,0,0};
    #pragma unroll
    for (int i = 0; i < 4; i++) {
        #pragma unroll
        for (int j = 0; j < 4; j++) {
            float h = fmaxf(hv[i][j] + bj[j], 0.0f);
            p3[i] = fmaf(h, w3v[j], p3[i]);
            p4[i] = fmaf(h, w4v[j], p4[i]);
            p5[i] = fmaf(h, w5v[j], p5[i]);
            p6[i] = fmaf(h, w6v[j], p6[i]);
        }
    }
    #pragma unroll
    for (int off = 16; off; off >>= 1) {
        #pragma unroll
        for (int i = 0; i < 4; i++) {
            p3[i] += __shfl_xor_sync(0xffffffffu, p3[i], off);
            p4[i] += __shfl_xor_sync(0xffffffffu, p4[i], off);
            p5[i] += __shfl_xor_sync(0xffffffffu, p5[i], off);
            p6[i] += __shfl_xor_sync(0xffffffffu, p6[i], off);
        }
    }

    if (lane < 4) {
        int i = lane;
        int task = mbase + m0 + i;
        if (task < T) {
            float2 sc = scalS[m0 + i];
            float me = sc.x;
            float se = sc.y;
            float y51 = 1.0f / (1.0f + expf(-(p3[i] * me + b3[0])));
            float y61 = p4[i] * me + b4[0];
            float y52 = 1.0f / (1.0f + expf(-(p5[i] * se + b5[0])));
            float y62 = p6[i] * se + b6[0];
            float p = y51 * y52;
            out[task] = (1.0f - p) * (-100.0f) + p * (y61 + y62);
        }
    }
}

// ---------------------------------------------------------------------------
extern "C" void kernel_launch(void* const* d_in, const int* in_sizes, int n_in,
                              void* d_out, int out_size) {
    const float* bb    = (const float*)d_in[2];
    const float* res   = (const float*)d_in[3];
    const float* fr    = (const float*)d_in[4];
    const float* estep = (const float*)d_in[5];
    const float* enode = (const float*)d_in[6];
    const float* ccl   = (const float*)d_in[7];
    const float* cnd   = (const float*)d_in[8];
    const float* W1    = (const float*)d_in[9];
    const float* b1    = (const float*)d_in[10];
    const float* W3    = (const float*)d_in[11];
    const float* b3    = (const float*)d_in[12];
    const float* W4    = (const float*)d_in[13];
    const float* b4    = (const float*)d_in[14];
    const float* W5    = (const float*)d_in[15];
    const float* b5    = (const float*)d_in[16];
    const float* W6    = (const float*)d_in[17];
    const float* b6    = (const float*)d_in[18];

    int T = in_sizes[2] / D_BB;

    int grid = (T + 31) / 32;
    critic_fused<<<grid, 256>>>(bb, res, fr, estep, enode, ccl, cnd,
                                W1, b1, W3, b3, W4, b4, W5, b5, W6, b6,
                                (float*)d_out, T);
}

// round 3
// speedup vs baseline: 1.5972x; 1.1396x over previous
#include <cuda_runtime.h>
#include <math.h>

#define MAXT 4096
#define D_BB 768
#define K1   160          // padded features (150 real + 10 zero)
#define NCHT 58           // total chunks of 16 (928 = 160 + 768)
#define KQN  4            // K-split factor

typedef unsigned long long u64;

__device__ float g_part[KQN * MAXT * 128];   // fp32 partial h per K-quarter

// ---- packed f32x2 helpers ---------------------------------------------------
__device__ __forceinline__ u64 dup2(float v) {
    u64 r; asm("mov.b64 %0, {%1, %1};" : "=l"(r) : "f"(v)); return r;
}
__device__ __forceinline__ void fma2(u64 &d, u64 a, u64 b) {
    asm("fma.rn.f32x2 %0, %1, %2, %0;" : "+l"(d) : "l"(a), "l"(b));
}
__device__ __forceinline__ float2 unpack2(u64 v) {
    float lo, hi; asm("mov.b64 {%0, %1}, %2;" : "=f"(lo), "=f"(hi) : "l"(v));
    return make_float2(lo, hi);
}

__constant__ int c_cbeg[KQN] = {0, 15, 30, 44};
__constant__ int c_cend[KQN] = {15, 30, 44, 58};

// -----------------------------------------------------------------------------
// GEMM kernel: grid (T/32, 4). CTA = 256 threads, 32 tasks x 128 cols,
// K-quarter given by blockIdx.y. Double-buffered smem, 1 sync per chunk.
// Warp layout: 8 rows x 64 cols (lane>>4 -> row half, lane&15 -> col group).
// -----------------------------------------------------------------------------
__global__ void __launch_bounds__(256, 4)
critic_gemm(const float* __restrict__ bb,
            const float* __restrict__ res, const float* __restrict__ fr,
            const float* __restrict__ estep,
            const float* __restrict__ W1, int T)
{
    __shared__ __align__(16) float featT[K1][32];     // [k][m]
    __shared__ __align__(16) float Xs[2][16][34];
    __shared__ __align__(16) float Ws[2][16][128];

    const int tid   = threadIdx.x;
    const int lane  = tid & 31;
    const int w     = tid >> 5;
    const int mbase = blockIdx.x * 32;
    const int kq    = blockIdx.y;
    const int cbeg  = c_cbeg[kq];
    const int cend  = c_cend[kq];

    // compute-tile mapping: 4 rows x 4 cols per thread
    const int m0 = (w & 3) * 8 + (lane >> 4) * 4;
    const int n0 = (w >> 2) * 64 + (lane & 15) * 4;

    // ---- features (only K-quarter 0 uses them) ----
    if (kq == 0) {
        for (int i = tid; i < 32 * K1; i += 256) {
            int m = i & 31;
            int idx = i >> 5;
            int task = mbase + m; if (task >= T) task = T - 1;
            float v = 0.0f;
            if (idx < 150) {
                int n = idx / 30, rem = idx - n * 30;
                int mm = rem / 6, o = rem - mm * 6;
                v = res[task * 5 + n] * fr[task * 5 + mm] * estep[task * 6 + o];
            }
            featT[idx][m] = v;
        }
    }

    // ---- loader mappings ----
    const int wkk = tid >> 4;           // W k-row in chunk (0..15)
    const int wc  = (tid & 15) * 8;     // 8 floats
    const int lkk = tid & 15;           // X k in chunk
    const int lm  = tid >> 4;           // X row (0..15), also +16
    int xt0 = mbase + lm;      if (xt0 >= T) xt0 = T - 1;
    int xt1 = mbase + lm + 16; if (xt1 >= T) xt1 = T - 1;
    const float* bb0 = bb + (size_t)xt0 * D_BB + lkk;
    const float* bb1 = bb + (size_t)xt1 * D_BB + lkk;

    auto ldw = [&](int c, float4 &a, float4 &b) {
        int row = c * 16 + wkk;
        a = make_float4(0.f, 0.f, 0.f, 0.f); b = a;
        int sr = (row < 160) ? row : row - 10;   // 918 -> 928 remap
        if (row < 150 || row >= 160) {
            const float* p = W1 + (size_t)sr * 128 + wc;
            a = *(const float4*)p;
            b = *(const float4*)(p + 4);
        }
    };

    u64 acc[2][4];
    #pragma unroll
    for (int p = 0; p < 2; p++)
        #pragma unroll
        for (int j = 0; j < 4; j++) acc[p][j] = 0ull;

    // ---- prologue: chunk cbeg -> buf0; prefetch cbeg+1 ----
    float4 wa, wb; float x0 = 0.f, x1 = 0.f;
    ldw(cbeg, wa, wb);
    if (cbeg >= 10) { int k = cbeg * 16 - K1; x0 = bb0[k]; x1 = bb1[k]; }
    *(float4*)&Ws[0][wkk][wc]     = wa;
    *(float4*)&Ws[0][wkk][wc + 4] = wb;
    if (cbeg >= 10) { Xs[0][lkk][lm] = x0; Xs[0][lkk][lm + 16] = x1; }
    if (cbeg + 1 < cend) {
        ldw(cbeg + 1, wa, wb);
        if (cbeg + 1 >= 10) { int k = (cbeg + 1) * 16 - K1; x0 = bb0[k]; x1 = bb1[k]; }
    }
    __syncthreads();   // featT + buf0 ready

    int pb = 1;
    for (int c = cbeg; c < cend; c++) {
        // store prefetched chunk c+1 into buf[pb] (free: last computed c-1)
        if (c + 1 < cend) {
            *(float4*)&Ws[pb][wkk][wc]     = wa;
            *(float4*)&Ws[pb][wkk][wc + 4] = wb;
            if (c + 1 >= 10) { Xs[pb][lkk][lm] = x0; Xs[pb][lkk][lm + 16] = x1; }
        }
        // prefetch chunk c+2
        if (c + 2 < cend) {
            ldw(c + 2, wa, wb);
            if (c + 2 >= 10) { int k = (c + 2) * 16 - K1; x0 = bb0[k]; x1 = bb1[k]; }
        }
        // compute chunk c
        const int cb = pb ^ 1;
        if (c < 10) {
            const float* xp = &featT[c * 16][0];
            #pragma unroll
            for (int kk = 0; kk < 16; kk++) {
                u64 xa = *(const u64*)(xp + kk * 32 + m0);
                u64 xb = *(const u64*)(xp + kk * 32 + m0 + 2);
                float4 wv = *(const float4*)&Ws[cb][kk][n0];
                u64 w0 = dup2(wv.x), w1 = dup2(wv.y), w2 = dup2(wv.z), w3 = dup2(wv.w);
                fma2(acc[0][0], xa, w0); fma2(acc[0][1], xa, w1);
                fma2(acc[0][2], xa, w2); fma2(acc[0][3], xa, w3);
                fma2(acc[1][0], xb, w0); fma2(acc[1][1], xb, w1);
                fma2(acc[1][2], xb, w2); fma2(acc[1][3], xb, w3);
            }
        } else {
            #pragma unroll
            for (int kk = 0; kk < 16; kk++) {
                u64 xa = *(const u64*)(&Xs[cb][kk][m0]);
                u64 xb = *(const u64*)(&Xs[cb][kk][m0 + 2]);
                float4 wv = *(const float4*)&Ws[cb][kk][n0];
                u64 w0 = dup2(wv.x), w1 = dup2(wv.y), w2 = dup2(wv.z), w3 = dup2(wv.w);
                fma2(acc[0][0], xa, w0); fma2(acc[0][1], xa, w1);
                fma2(acc[0][2], xa, w2); fma2(acc[0][3], xa, w3);
                fma2(acc[1][0], xb, w0); fma2(acc[1][1], xb, w1);
                fma2(acc[1][2], xb, w2); fma2(acc[1][3], xb, w3);
            }
        }
        __syncthreads();
        pb ^= 1;
    }

    // ---- store partials: 4 rows x 4 cols per thread ----
    float hv[4][4];
    #pragma unroll
    for (int j = 0; j < 4; j++) {
        float2 lo = unpack2(acc[0][j]);
        float2 hi = unpack2(acc[1][j]);
        hv[0][j] = lo.x; hv[1][j] = lo.y; hv[2][j] = hi.x; hv[3][j] = hi.y;
    }
    #pragma unroll
    for (int i = 0; i < 4; i++) {
        int task = mbase + m0 + i;
        if (task < T) {
            float4 v = make_float4(hv[i][0], hv[i][1], hv[i][2], hv[i][3]);
            *(float4*)&g_part[((size_t)kq * MAXT + task) * 128 + n0] = v;
        }
    }
}

// -----------------------------------------------------------------------------
// Epilogue: one warp per task. Sum 4 partial slabs, bias+relu, 4 dots,
// per-task scalar reductions, final combine.
// -----------------------------------------------------------------------------
__global__ void __launch_bounds__(256)
critic_epi(const float* __restrict__ enode, const float* __restrict__ ccl,
           const float* __restrict__ cnd,
           const float* __restrict__ b1,
           const float* __restrict__ W3, const float* __restrict__ b3,
           const float* __restrict__ W4, const float* __restrict__ b4,
           const float* __restrict__ W5, const float* __restrict__ b5,
           const float* __restrict__ W6, const float* __restrict__ b6,
           float* __restrict__ out, int T)
{
    int t = blockIdx.x * 8 + (threadIdx.x >> 5);
    int lane = threadIdx.x & 31;
    if (t >= T) return;
    int n0 = lane * 4;

    float4 s = *(const float4*)&g_part[((size_t)0 * MAXT + t) * 128 + n0];
    #pragma unroll
    for (int q = 1; q < KQN; q++) {
        float4 p = *(const float4*)&g_part[((size_t)q * MAXT + t) * 128 + n0];
        s.x += p.x; s.y += p.y; s.z += p.z; s.w += p.w;
    }
    float4 bj = *(const float4*)&b1[n0];
    float h[4] = { fmaxf(s.x + bj.x, 0.f), fmaxf(s.y + bj.y, 0.f),
                   fmaxf(s.z + bj.z, 0.f), fmaxf(s.w + bj.w, 0.f) };

    float4 w3 = *(const float4*)&W3[n0];
    float4 w4 = *(const float4*)&W4[n0];
    float4 w5 = *(const float4*)&W5[n0];
    float4 w6 = *(const float4*)&W6[n0];
    float p3 = h[0]*w3.x + h[1]*w3.y + h[2]*w3.z + h[3]*w3.w;
    float p4 = h[0]*w4.x + h[1]*w4.y + h[2]*w4.z + h[3]*w4.w;
    float p5 = h[0]*w5.x + h[1]*w5.y + h[2]*w5.z + h[3]*w5.w;
    float p6 = h[0]*w6.x + h[1]*w6.y + h[2]*w6.z + h[3]*w6.w;

    float se = enode[(size_t)t * 64 + lane] + enode[(size_t)t * 64 + lane + 32];
    float sc = (lane < 4) ? ccl[t * 4 + lane] : 0.0f;
    float sn = cnd[(size_t)t * 32 + lane];

    #pragma unroll
    for (int off = 16; off; off >>= 1) {
        p3 += __shfl_xor_sync(0xffffffffu, p3, off);
        p4 += __shfl_xor_sync(0xffffffffu, p4, off);
        p5 += __shfl_xor_sync(0xffffffffu, p5, off);
        p6 += __shfl_xor_sync(0xffffffffu, p6, off);
        se += __shfl_xor_sync(0xffffffffu, se, off);
        sc += __shfl_xor_sync(0xffffffffu, sc, off);
        sn += __shfl_xor_sync(0xffffffffu, sn, off);
    }

    if (lane == 0) {
        float me = se * (1.0f / 64.0f);
        float ss = sc * sn;
        float y51 = 1.0f / (1.0f + expf(-(p3 * me + b3[0])));
        float y61 = p4 * me + b4[0];
        float y52 = 1.0f / (1.0f + expf(-(p5 * ss + b5[0])));
        float y62 = p6 * ss + b6[0];
        float p = y51 * y52;
        out[t] = (1.0f - p) * (-100.0f) + p * (y61 + y62);
    }
}

// -----------------------------------------------------------------------------
extern "C" void kernel_launch(void* const* d_in, const int* in_sizes, int n_in,
                              void* d_out, int out_size) {
    const float* bb    = (const float*)d_in[2];
    const float* res   = (const float*)d_in[3];
    const float* fr    = (const float*)d_in[4];
    const float* estep = (const float*)d_in[5];
    const float* enode = (const float*)d_in[6];
    const float* ccl   = (const float*)d_in[7];
    const float* cnd   = (const float*)d_in[8];
    const float* W1    = (const float*)d_in[9];
    const float* b1    = (const float*)d_in[10];
    const float* W3    = (const float*)d_in[11];
    const float* b3    = (const float*)d_in[12];
    const float* W4    = (const float*)d_in[13];
    const float* b4    = (const float*)d_in[14];
    const float* W5    = (const float*)d_in[15];
    const float* b5    = (const float*)d_in[16];
    const float* W6    = (const float*)d_in[17];
    const float* b6    = (const float*)d_in[18];

    int T = in_sizes[2] / D_BB;
    if (T > MAXT) T = MAXT;

    dim3 grid((T + 31) / 32, KQN);
    critic_gemm<<<grid, 256>>>(bb, res, fr, estep, W1, T);
    critic_epi<<<(T + 7) / 8, 256>>>(enode, ccl, cnd, b1, W3, b3, W4, b4,
                                     W5, b5, W6, b6, (float*)d_out, T);
}

// round 5
// speedup vs baseline: 2.2410x; 1.4031x over previous
#include <cuda_runtime.h>
#include <cuda_bf16.h>
#include <math.h>
#include <stdint.h>

#define D_BB 768
#define KPAD 960          // 160 feat(+pad) + 768 bb + 32 pad
#define CH   64           // k per chunk
#define NCH  15           // chunks
#define NSTG 3            // smem pipeline stages
#define BUFB 40960        // bytes per stage: Ah 4K | Al 4K | Bh 16K | Bl 16K
#define SMEM_TOTAL (NSTG * BUFB)

typedef unsigned long long u64;
typedef unsigned int       u32;

// ---- W1 pre-split to bf16 hi/lo, transposed [n][k] --------------------------
__device__ __align__(16) __nv_bfloat16 g_Bh[128 * KPAD];
__device__ __align__(16) __nv_bfloat16 g_Bl[128 * KPAD];

// ---- helpers -----------------------------------------------------------------
__device__ __forceinline__ u32 smem_u32(const void* p) {
    u32 a;
    asm("{ .reg .u64 t; cvta.to.shared.u64 t, %1; cvt.u32.u64 %0, t; }"
        : "=r"(a) : "l"(p));
    return a;
}
__device__ __forceinline__ u32 SWZ(u32 b) { return b ^ ((b >> 3) & 0x70); }

__device__ __forceinline__ u32 pack_bf2(float lo, float hi) {
    __nv_bfloat162 v = __floats2bfloat162_rn(lo, hi);   // lo->x, hi->y
    return *(u32*)&v;
}
__device__ __forceinline__ float bfr(float x) {         // round-trip through bf16
    return __bfloat162float(__float2bfloat16_rn(x));
}

#define LDMX4(r, addr) \
    asm volatile("ldmatrix.sync.aligned.m8n8.x4.shared.b16 {%0,%1,%2,%3}, [%4];" \
        : "=r"((r)[0]), "=r"((r)[1]), "=r"((r)[2]), "=r"((r)[3]) : "r"(addr))

#define MMA16816(d, a, b0, b1) \
    asm volatile("mma.sync.aligned.m16n8k16.row.col.f32.bf16.bf16.f32 " \
        "{%0,%1,%2,%3}, {%4,%5,%6,%7}, {%8,%9}, {%0,%1,%2,%3};" \
        : "+f"((d)[0]), "+f"((d)[1]), "+f"((d)[2]), "+f"((d)[3]) \
        : "r"((a)[0]), "r"((a)[1]), "r"((a)[2]), "r"((a)[3]), "r"(b0), "r"(b1))

#define CPA16(dst, src) \
    asm volatile("cp.async.cg.shared.global [%0], [%1], 16;" \
        :: "r"(dst), "l"(src) : "memory")
#define CPA_COMMIT() asm volatile("cp.async.commit_group;" ::: "memory")
#define CPA_WAIT(n)  asm volatile("cp.async.wait_group %0;" :: "n"(n) : "memory")

#define STS128(r0, r1, r2, r3, sa) \
    asm volatile("st.shared.v4.b32 [%0], {%1, %2, %3, %4};" \
        :: "r"(sa), "r"(r0), "r"(r1), "r"(r2), "r"(r3) : "memory")

// -----------------------------------------------------------------------------
// Prep: W1 [918,128] fp32 -> g_Bh/g_Bl [128 n][960 k] bf16 (rows 150-159 and
// 928-959 zero; 918-row source remapped).
// -----------------------------------------------------------------------------
__global__ void prep_B(const float* __restrict__ W1) {
    int id = blockIdx.x * 256 + threadIdx.x;        // 128 n * 240 groups of 4
    if (id >= 128 * 240) return;
    int n  = id / 240;
    int k4 = (id % 240) * 4;
    u32 hw[2], lw[2];
    #pragma unroll
    for (int p = 0; p < 2; p++) {
        float v0 = 0.f, v1 = 0.f;
        int g0 = k4 + p * 2, g1 = g0 + 1;
        if (g0 < 150)                    v0 = W1[(size_t)g0 * 128 + n];
        else if (g0 >= 160 && g0 < 928)  v0 = W1[(size_t)(g0 - 10) * 128 + n];
        if (g1 < 150)                    v1 = W1[(size_t)g1 * 128 + n];
        else if (g1 >= 160 && g1 < 928)  v1 = W1[(size_t)(g1 - 10) * 128 + n];
        float h0 = bfr(v0), h1 = bfr(v1);
        hw[p] = pack_bf2(v0, v1);
        lw[p] = pack_bf2(v0 - h0, v1 - h1);
    }
    *(u64*)&g_Bh[(size_t)n * KPAD + k4] = (u64)hw[0] | ((u64)hw[1] << 32);
    *(u64*)&g_Bl[(size_t)n * KPAD + k4] = (u64)lw[0] | ((u64)lw[1] << 32);
}

// -----------------------------------------------------------------------------
// Fused kernel: grid = T/32 CTAs, 256 threads (8 warps: 2 M x 4 N).
// Per CTA: h[32x128] = relu(x @ W1 + b1) via 3-pass bf16 mma.sync, then full
// epilogue for its own 32 tasks.
// -----------------------------------------------------------------------------
__global__ void __launch_bounds__(256)
critic_mma(const float* __restrict__ bb,
           const float* __restrict__ res,   const float* __restrict__ fr,
           const float* __restrict__ estep, const float* __restrict__ enode,
           const float* __restrict__ ccl,   const float* __restrict__ cnd,
           const float* __restrict__ b1,
           const float* __restrict__ W3, const float* __restrict__ b3,
           const float* __restrict__ W4, const float* __restrict__ b4,
           const float* __restrict__ W5, const float* __restrict__ b5,
           const float* __restrict__ W6, const float* __restrict__ b6,
           float* __restrict__ out, int T)
{
    extern __shared__ __align__(16) char dsm[];
    const u32 sb = smem_u32(dsm);

    const int tid  = threadIdx.x;
    const int lane = tid & 31;
    const int wid  = tid >> 5;
    const int mbase = blockIdx.x * 32;

    // warp tile: m0w in {0,16}, n0w in {0,32,64,96}
    const int m0w = (wid & 1) * 16;
    const int n0w = (wid >> 1) * 32;

    // ---- A loader mapping: thread -> (row, 8 consecutive k) ----
    const int ar = tid >> 3;               // 0..31
    const int ak = (tid & 7) * 8;          // 0..56
    int atask = mbase + ar; if (atask >= T) atask = T - 1;
    const float* bbrow = bb + (size_t)atask * D_BB;
    const u32 aoff = SWZ((u32)(ar * 128 + ak * 2));

    // ---- B loader mapping: thread -> (n, 32 k) ----
    const int bn = tid >> 1;
    const int bk = (tid & 1) * 32;
    const __nv_bfloat16* bsrch = g_Bh + (size_t)bn * KPAD + bk;
    const __nv_bfloat16* bsrcl = g_Bl + (size_t)bn * KPAD + bk;
    u32 boff[4];
    #pragma unroll
    for (int i = 0; i < 4; i++) boff[i] = SWZ((u32)(bn * 128 + bk * 2 + i * 16));

    // ---- fragment address bases (per lane) ----
    const u32 aRowByte = (u32)((m0w + (lane & 7) + ((lane >> 3) & 1) * 8) * 128
                               + (lane >> 4) * 16);
    u32 bRowByte[2];
    #pragma unroll
    for (int g2 = 0; g2 < 2; g2++)
        bRowByte[g2] = (u32)((n0w + g2 * 16 + (lane >> 4) * 8 + (lane & 7)) * 128
                             + ((lane >> 3) & 1) * 16);

    float D[4][4];
    #pragma unroll
    for (int i = 0; i < 4; i++)
        #pragma unroll
        for (int j = 0; j < 4; j++) D[i][j] = 0.f;

    // ---- chunk issue: A (LDG+cvt+STS) and B (cp.async) into stage s ----
    auto issue = [&](int c) {
        const u32 base = sb + (u32)(c % NSTG) * BUFB;
        const u32 sAh = base, sAl = base + 4096, sBh = base + 8192, sBl = base + 24576;

        // A
        int g0 = c * CH + ak;
        float x[8];
        if (g0 >= 160 && g0 + 8 <= 928) {
            const float4* p = (const float4*)(bbrow + (g0 - 160));
            float4 v0 = p[0], v1 = p[1];
            x[0]=v0.x; x[1]=v0.y; x[2]=v0.z; x[3]=v0.w;
            x[4]=v1.x; x[5]=v1.y; x[6]=v1.z; x[7]=v1.w;
        } else {
            #pragma unroll
            for (int j = 0; j < 8; j++) {
                int gk = g0 + j;
                float v = 0.f;
                if (gk < 150) {
                    int nn = gk / 30, rem = gk - nn * 30;
                    int mm = rem / 6, oo = rem - mm * 6;
                    v = res[atask * 5 + nn] * fr[atask * 5 + mm] * estep[atask * 6 + oo];
                } else if (gk >= 160 && gk < 928) {
                    v = bbrow[gk - 160];
                }
                x[j] = v;
            }
        }
        u32 hw[4], lw[4];
        #pragma unroll
        for (int q = 0; q < 4; q++) {
            float x0 = x[2*q], x1 = x[2*q+1];
            float h0 = bfr(x0), h1 = bfr(x1);
            hw[q] = pack_bf2(x0, x1);
            lw[q] = pack_bf2(x0 - h0, x1 - h1);
        }
        STS128(hw[0], hw[1], hw[2], hw[3], sAh + aoff);
        STS128(lw[0], lw[1], lw[2], lw[3], sAl + aoff);

        // B (async)
        const __nv_bfloat16* sh = bsrch + c * CH;
        const __nv_bfloat16* sl = bsrcl + c * CH;
        #pragma unroll
        for (int i = 0; i < 4; i++) {
            CPA16(sBh + boff[i], sh + i * 8);
            CPA16(sBl + boff[i], sl + i * 8);
        }
    };

    auto compute = [&](int c) {
        const u32 base = sb + (u32)(c % NSTG) * BUFB;
        const u32 sAh = base, sAl = base + 4096, sBh = base + 8192, sBl = base + 24576;
        #pragma unroll
        for (int ks = 0; ks < 4; ks++) {
            const u32 ao = SWZ(aRowByte + ks * 32);
            u32 a_h[4], a_l[4];
            LDMX4(a_h, sAh + ao);
            LDMX4(a_l, sAl + ao);
            #pragma unroll
            for (int g2 = 0; g2 < 2; g2++) {
                const u32 bo = SWZ(bRowByte[g2] + ks * 32);
                u32 b_h[4], b_l[4];
                LDMX4(b_h, sBh + bo);
                LDMX4(b_l, sBl + bo);
                MMA16816(D[g2*2],   a_h, b_h[0], b_h[1]);
                MMA16816(D[g2*2],   a_h, b_l[0], b_l[1]);
                MMA16816(D[g2*2],   a_l, b_h[0], b_h[1]);
                MMA16816(D[g2*2+1], a_h, b_h[2], b_h[3]);
                MMA16816(D[g2*2+1], a_h, b_l[2], b_l[3]);
                MMA16816(D[g2*2+1], a_l, b_h[2], b_h[3]);
            }
        }
    };

    // ---- pipeline: 3 stages, 1 sync per chunk ----
    issue(0); CPA_COMMIT();
    issue(1); CPA_COMMIT();
    CPA_WAIT(1);
    __syncthreads();

    for (int c = 0; c < NCH; c++) {
        compute(c);
        if (c + 2 < NCH) { issue(c + 2); CPA_COMMIT(); }
        if (c + 2 < NCH) { CPA_WAIT(1); } else { CPA_WAIT(0); }
        __syncthreads();
    }

    // ---- stage D to smem (raw pre-activation), then per-task epilogue ----
    float* hsm = (float*)dsm;               // [32][132]
    const int g = lane >> 2, t = lane & 3;
    #pragma unroll
    for (int ng = 0; ng < 4; ng++) {
        int col = n0w + ng * 8 + 2 * t;
        *(float2*)&hsm[(m0w + g) * 132 + col]     = make_float2(D[ng][0], D[ng][1]);
        *(float2*)&hsm[(m0w + g + 8) * 132 + col] = make_float2(D[ng][2], D[ng][3]);
    }
    __syncthreads();

    const int n0 = lane * 4;
    const float4 bj = *(const float4*)&b1[n0];
    const float4 w3 = *(const float4*)&W3[n0];
    const float4 w4 = *(const float4*)&W4[n0];
    const float4 w5 = *(const float4*)&W5[n0];
    const float4 w6 = *(const float4*)&W6[n0];
    const float B3 = b3[0], B4 = b4[0], B5 = b5[0], B6 = b6[0];

    #pragma unroll
    for (int it = 0; it < 4; it++) {
        int m = wid * 4 + it;
        int task = mbase + m;
        bool ok = (task < T);
        int rt = ok ? task : (T - 1);

        float4 s = *(const float4*)&hsm[m * 132 + n0];
        float h0 = fmaxf(s.x + bj.x, 0.f), h1 = fmaxf(s.y + bj.y, 0.f);
        float h2 = fmaxf(s.z + bj.z, 0.f), h3 = fmaxf(s.w + bj.w, 0.f);
        float p3 = h0*w3.x + h1*w3.y + h2*w3.z + h3*w3.w;
        float p4 = h0*w4.x + h1*w4.y + h2*w4.z + h3*w4.w;
        float p5 = h0*w5.x + h1*w5.y + h2*w5.z + h3*w5.w;
        float p6 = h0*w6.x + h1*w6.y + h2*w6.z + h3*w6.w;

        float se = enode[(size_t)rt * 64 + lane] + enode[(size_t)rt * 64 + lane + 32];
        float sc = (lane < 4) ? ccl[rt * 4 + lane] : 0.0f;
        float sn = cnd[(size_t)rt * 32 + lane];

        #pragma unroll
        for (int off = 16; off; off >>= 1) {
            p3 += __shfl_xor_sync(0xffffffffu, p3, off);
            p4 += __shfl_xor_sync(0xffffffffu, p4, off);
            p5 += __shfl_xor_sync(0xffffffffu, p5, off);
            p6 += __shfl_xor_sync(0xffffffffu, p6, off);
            se += __shfl_xor_sync(0xffffffffu, se, off);
            sc += __shfl_xor_sync(0xffffffffu, sc, off);
            sn += __shfl_xor_sync(0xffffffffu, sn, off);
        }
        if (lane == 0 && ok) {
            float me = se * (1.0f / 64.0f);
            float ss = sc * sn;
            float y51 = 1.0f / (1.0f + expf(-(p3 * me + B3)));
            float y61 = p4 * me + B4;
            float y52 = 1.0f / (1.0f + expf(-(p5 * ss + B5)));
            float y62 = p6 * ss + B6;
            float p = y51 * y52;
            out[task] = (1.0f - p) * (-100.0f) + p * (y61 + y62);
        }
    }
}

// -----------------------------------------------------------------------------
extern "C" void kernel_launch(void* const* d_in, const int* in_sizes, int n_in,
                              void* d_out, int out_size) {
    const float* bb    = (const float*)d_in[2];
    const float* res   = (const float*)d_in[3];
    const float* fr    = (const float*)d_in[4];
    const float* estep = (const float*)d_in[5];
    const float* enode = (const float*)d_in[6];
    const float* ccl   = (const float*)d_in[7];
    const float* cnd   = (const float*)d_in[8];
    const float* W1    = (const float*)d_in[9];
    const float* b1    = (const float*)d_in[10];
    const float* W3    = (const float*)d_in[11];
    const float* b3    = (const float*)d_in[12];
    const float* W4    = (const float*)d_in[13];
    const float* b4    = (const float*)d_in[14];
    const float* W5    = (const float*)d_in[15];
    const float* b5    = (const float*)d_in[16];
    const float* W6    = (const float*)d_in[17];
    const float* b6    = (const float*)d_in[18];

    int T = in_sizes[2] / D_BB;

    static int cfg = 0;
    if (!cfg) {
        cudaFuncSetAttribute(critic_mma,
                             cudaFuncAttributeMaxDynamicSharedMemorySize,
                             SMEM_TOTAL);
        cfg = 1;
    }

    prep_B<<<120, 256>>>(W1);
    critic_mma<<<(T + 31) / 32, 256, SMEM_TOTAL>>>(
        bb, res, fr, estep, enode, ccl, cnd,
        b1, W3, b3, W4, b4, W5, b5, W6, b6, (float*)d_out, T);
}

// round 6
// speedup vs baseline: 2.7905x; 1.2452x over previous
#include <cuda_runtime.h>
#include <cuda_bf16.h>
#include <math.h>
#include <stdint.h>

#define D_BB 768
#define KPAD 960          // 160 feat(+pad) + 768 bb + 32 pad
#define CH   64           // k per chunk
#define NCH  15           // chunks
#define NSTG 3            // smem pipeline stages
#define BUFB 40960        // bytes per stage: Ah 4K | Al 4K | Bh 16K | Bl 16K
#define SMEM_TOTAL (NSTG * BUFB)

typedef unsigned long long u64;
typedef unsigned int       u32;

// ---- W1 pre-split to bf16 hi/lo, transposed [n][k] --------------------------
__device__ __align__(16) __nv_bfloat16 g_Bh[128 * KPAD];
__device__ __align__(16) __nv_bfloat16 g_Bl[128 * KPAD];

// ---- helpers -----------------------------------------------------------------
__device__ __forceinline__ u32 smem_u32(const void* p) {
    u32 a;
    asm("{ .reg .u64 t; cvta.to.shared.u64 t, %1; cvt.u32.u64 %0, t; }"
        : "=r"(a) : "l"(p));
    return a;
}
__device__ __forceinline__ u32 SWZ(u32 b) { return b ^ ((b >> 3) & 0x70); }

__device__ __forceinline__ u32 pack_bf2(float lo, float hi) {
    __nv_bfloat162 v = __floats2bfloat162_rn(lo, hi);
    return *(u32*)&v;
}
__device__ __forceinline__ float bfr(float x) {
    return __bfloat162float(__float2bfloat16_rn(x));
}

#define LDMX4(r, addr) \
    asm volatile("ldmatrix.sync.aligned.m8n8.x4.shared.b16 {%0,%1,%2,%3}, [%4];" \
        : "=r"((r)[0]), "=r"((r)[1]), "=r"((r)[2]), "=r"((r)[3]) : "r"(addr))

#define MMA16816(d, a, b0, b1) \
    asm volatile("mma.sync.aligned.m16n8k16.row.col.f32.bf16.bf16.f32 " \
        "{%0,%1,%2,%3}, {%4,%5,%6,%7}, {%8,%9}, {%0,%1,%2,%3};" \
        : "+f"((d)[0]), "+f"((d)[1]), "+f"((d)[2]), "+f"((d)[3]) \
        : "r"((a)[0]), "r"((a)[1]), "r"((a)[2]), "r"((a)[3]), "r"(b0), "r"(b1))

#define CPA16(dst, src) \
    asm volatile("cp.async.cg.shared.global [%0], [%1], 16;" \
        :: "r"(dst), "l"(src) : "memory")
#define CPA_COMMIT() asm volatile("cp.async.commit_group;" ::: "memory")
#define CPA_WAIT(n)  asm volatile("cp.async.wait_group %0;" :: "n"(n) : "memory")

#define STS64(r0, r1, sa) \
    asm volatile("st.shared.v2.b32 [%0], {%1, %2};" \
        :: "r"(sa), "r"(r0), "r"(r1) : "memory")

// -----------------------------------------------------------------------------
// Prep: W1 [918,128] fp32 -> g_Bh/g_Bl [128 n][960 k] bf16 split (row remap).
// -----------------------------------------------------------------------------
__global__ void prep_B(const float* __restrict__ W1) {
    int id = blockIdx.x * 256 + threadIdx.x;        // 128 n * 240 groups of 4
    if (id >= 128 * 240) return;
    int n  = id / 240;
    int k4 = (id % 240) * 4;
    u32 hw[2], lw[2];
    #pragma unroll
    for (int p = 0; p < 2; p++) {
        float v0 = 0.f, v1 = 0.f;
        int g0 = k4 + p * 2, g1 = g0 + 1;
        if (g0 < 150)                    v0 = W1[(size_t)g0 * 128 + n];
        else if (g0 >= 160 && g0 < 928)  v0 = W1[(size_t)(g0 - 10) * 128 + n];
        if (g1 < 150)                    v1 = W1[(size_t)g1 * 128 + n];
        else if (g1 >= 160 && g1 < 928)  v1 = W1[(size_t)(g1 - 10) * 128 + n];
        float h0 = bfr(v0), h1 = bfr(v1);
        hw[p] = pack_bf2(v0, v1);
        lw[p] = pack_bf2(v0 - h0, v1 - h1);
    }
    *(u64*)&g_Bh[(size_t)n * KPAD + k4] = (u64)hw[0] | ((u64)hw[1] << 32);
    *(u64*)&g_Bl[(size_t)n * KPAD + k4] = (u64)lw[0] | ((u64)lw[1] << 32);
}

// -----------------------------------------------------------------------------
// Fused kernel: grid = T/32 CTAs, 512 threads (16 warps: 2 M x 8 N tiles).
// 3-pass bf16 split-precision mma.sync with independent accumulator sets.
// -----------------------------------------------------------------------------
__global__ void __launch_bounds__(512)
critic_mma(const float* __restrict__ bb,
           const float* __restrict__ res,   const float* __restrict__ fr,
           const float* __restrict__ estep, const float* __restrict__ enode,
           const float* __restrict__ ccl,   const float* __restrict__ cnd,
           const float* __restrict__ b1,
           const float* __restrict__ W3, const float* __restrict__ b3,
           const float* __restrict__ W4, const float* __restrict__ b4,
           const float* __restrict__ W5, const float* __restrict__ b5,
           const float* __restrict__ W6, const float* __restrict__ b6,
           float* __restrict__ out, int T)
{
    extern __shared__ __align__(16) char dsm[];
    const u32 sb = smem_u32(dsm);

    const int tid  = threadIdx.x;
    const int lane = tid & 31;
    const int wid  = tid >> 5;
    const int mbase = blockIdx.x * 32;

    // warp tile: m0w in {0,16}, n0w in {0,16,...,112}
    const int m0w = (wid & 1) * 16;
    const int n0w = (wid >> 1) * 16;

    // ---- A loader mapping: thread -> (row, 4 consecutive k) ----
    const int ar = tid >> 4;                // 0..31
    const int ak = (tid & 15) * 4;          // 0..60
    int atask = mbase + ar; if (atask >= T) atask = T - 1;
    const float* bbrow = bb + (size_t)atask * D_BB;
    const u32 aoff = SWZ((u32)(ar * 128 + ak * 2));

    // ---- B loader mapping: 2 x (row, 16B seg) per thread per buffer ----
    int brow[2], bseg[2]; u32 bdst[2];
    #pragma unroll
    for (int i = 0; i < 2; i++) {
        int id = tid + i * 512;
        brow[i] = id >> 3;
        bseg[i] = id & 7;
        bdst[i] = SWZ((u32)(brow[i] * 128 + bseg[i] * 16));
    }

    // ---- fragment address bases (per lane) ----
    const u32 aRowByte = (u32)((m0w + (lane & 7) + ((lane >> 3) & 1) * 8) * 128
                               + (lane >> 4) * 16);
    const u32 bRowByte = (u32)((n0w + (lane >> 4) * 8 + (lane & 7)) * 128
                               + ((lane >> 3) & 1) * 16);

    // independent accumulator sets: Da=AhBh, Db=AhBl, Dc=AlBh; 2 n-halves each
    float Da[2][4], Db[2][4], Dc[2][4];
    #pragma unroll
    for (int h = 0; h < 2; h++)
        #pragma unroll
        for (int j = 0; j < 4; j++) { Da[h][j] = 0.f; Db[h][j] = 0.f; Dc[h][j] = 0.f; }

    auto issue = [&](int c) {
        const u32 base = sb + (u32)(c % NSTG) * BUFB;
        const u32 sAh = base, sAl = base + 4096, sBh = base + 8192, sBl = base + 24576;

        // A: 4 fp32 -> bf16 hi/lo
        int g0 = c * CH + ak;
        float x[4];
        if (g0 >= 160 && g0 + 4 <= 928) {
            float4 v = *(const float4*)(bbrow + (g0 - 160));
            x[0] = v.x; x[1] = v.y; x[2] = v.z; x[3] = v.w;
        } else {
            #pragma unroll
            for (int j = 0; j < 4; j++) {
                int gk = g0 + j;
                float v = 0.f;
                if (gk < 150) {
                    int nn = gk / 30, rem = gk - nn * 30;
                    int mm = rem / 6, oo = rem - mm * 6;
                    v = res[atask * 5 + nn] * fr[atask * 5 + mm] * estep[atask * 6 + oo];
                } else if (gk >= 160 && gk < 928) {
                    v = bbrow[gk - 160];
                }
                x[j] = v;
            }
        }
        float h0 = bfr(x[0]), h1 = bfr(x[1]), h2 = bfr(x[2]), h3 = bfr(x[3]);
        STS64(pack_bf2(x[0], x[1]), pack_bf2(x[2], x[3]), sAh + aoff);
        STS64(pack_bf2(x[0] - h0, x[1] - h1), pack_bf2(x[2] - h2, x[3] - h3), sAl + aoff);

        // B: async copy pre-split tiles
        #pragma unroll
        for (int i = 0; i < 2; i++) {
            const size_t so = (size_t)brow[i] * KPAD + c * CH + bseg[i] * 8;
            CPA16(sBh + bdst[i], g_Bh + so);
            CPA16(sBl + bdst[i], g_Bl + so);
        }
    };

    auto compute = [&](int c) {
        const u32 base = sb + (u32)(c % NSTG) * BUFB;
        const u32 sAh = base, sAl = base + 4096, sBh = base + 8192, sBl = base + 24576;
        #pragma unroll
        for (int ks = 0; ks < 4; ks++) {
            const u32 ao = SWZ(aRowByte + ks * 32);
            const u32 bo = SWZ(bRowByte + ks * 32);
            u32 a_h[4], a_l[4], b_h[4], b_l[4];
            LDMX4(a_h, sAh + ao);
            LDMX4(b_h, sBh + bo);
            LDMX4(a_l, sAl + ao);
            LDMX4(b_l, sBl + bo);
            MMA16816(Da[0], a_h, b_h[0], b_h[1]);
            MMA16816(Db[0], a_h, b_l[0], b_l[1]);
            MMA16816(Dc[0], a_l, b_h[0], b_h[1]);
            MMA16816(Da[1], a_h, b_h[2], b_h[3]);
            MMA16816(Db[1], a_h, b_l[2], b_l[3]);
            MMA16816(Dc[1], a_l, b_h[2], b_h[3]);
        }
    };

    // ---- pipeline ----
    issue(0); CPA_COMMIT();
    issue(1); CPA_COMMIT();
    CPA_WAIT(1);
    __syncthreads();

    for (int c = 0; c < NCH; c++) {
        compute(c);
        if (c + 2 < NCH) { issue(c + 2); CPA_COMMIT(); CPA_WAIT(1); }
        else             { CPA_WAIT(0); }
        __syncthreads();
    }

    // ---- combine accumulator sets, stage to smem ----
    float* hsm = (float*)dsm;               // [32][132]
    const int drow = m0w + (lane >> 2);
    #pragma unroll
    for (int h = 0; h < 2; h++) {
        int col = n0w + h * 8 + 2 * (lane & 3);
        float d0 = Da[h][0] + Db[h][0] + Dc[h][0];
        float d1 = Da[h][1] + Db[h][1] + Dc[h][1];
        float d2 = Da[h][2] + Db[h][2] + Dc[h][2];
        float d3 = Da[h][3] + Db[h][3] + Dc[h][3];
        *(float2*)&hsm[drow * 132 + col]       = make_float2(d0, d1);
        *(float2*)&hsm[(drow + 8) * 132 + col] = make_float2(d2, d3);
    }
    __syncthreads();

    // ---- per-task epilogue: 16 warps x 2 tasks ----
    const int n0 = lane * 4;
    const float4 bj = *(const float4*)&b1[n0];
    const float4 w3 = *(const float4*)&W3[n0];
    const float4 w4 = *(const float4*)&W4[n0];
    const float4 w5 = *(const float4*)&W5[n0];
    const float4 w6 = *(const float4*)&W6[n0];
    const float B3 = b3[0], B4 = b4[0], B5 = b5[0], B6 = b6[0];

    #pragma unroll
    for (int it = 0; it < 2; it++) {
        int m = wid * 2 + it;
        int task = mbase + m;
        bool ok = (task < T);
        int rt = ok ? task : (T - 1);

        float4 s = *(const float4*)&hsm[m * 132 + n0];
        float h0 = fmaxf(s.x + bj.x, 0.f), h1 = fmaxf(s.y + bj.y, 0.f);
        float h2 = fmaxf(s.z + bj.z, 0.f), h3 = fmaxf(s.w + bj.w, 0.f);
        float p3 = h0*w3.x + h1*w3.y + h2*w3.z + h3*w3.w;
        float p4 = h0*w4.x + h1*w4.y + h2*w4.z + h3*w4.w;
        float p5 = h0*w5.x + h1*w5.y + h2*w5.z + h3*w5.w;
        float p6 = h0*w6.x + h1*w6.y + h2*w6.z + h3*w6.w;

        float se = enode[(size_t)rt * 64 + lane] + enode[(size_t)rt * 64 + lane + 32];
        float sc = (lane < 4) ? ccl[rt * 4 + lane] : 0.0f;
        float sn = cnd[(size_t)rt * 32 + lane];

        #pragma unroll
        for (int off = 16; off; off >>= 1) {
            p3 += __shfl_xor_sync(0xffffffffu, p3, off);
            p4 += __shfl_xor_sync(0xffffffffu, p4, off);
            p5 += __shfl_xor_sync(0xffffffffu, p5, off);
            p6 += __shfl_xor_sync(0xffffffffu, p6, off);
            se += __shfl_xor_sync(0xffffffffu, se, off);
            sc += __shfl_xor_sync(0xffffffffu, sc, off);
            sn += __shfl_xor_sync(0xffffffffu, sn, off);
        }
        if (lane == 0 && ok) {
            float me = se * (1.0f / 64.0f);
            float ss = sc * sn;
            float y51 = 1.0f / (1.0f + expf(-(p3 * me + B3)));
            float y61 = p4 * me + B4;
            float y52 = 1.0f / (1.0f + expf(-(p5 * ss + B5)));
            float y62 = p6 * ss + B6;
            float p = y51 * y52;
            out[task] = (1.0f - p) * (-100.0f) + p * (y61 + y62);
        }
    }
}

// -----------------------------------------------------------------------------
extern "C" void kernel_launch(void* const* d_in, const int* in_sizes, int n_in,
                              void* d_out, int out_size) {
    const float* bb    = (const float*)d_in[2];
    const float* res   = (const float*)d_in[3];
    const float* fr    = (const float*)d_in[4];
    const float* estep = (const float*)d_in[5];
    const float* enode = (const float*)d_in[6];
    const float* ccl   = (const float*)d_in[7];
    const float* cnd   = (const float*)d_in[8];
    const float* W1    = (const float*)d_in[9];
    const float* b1    = (const float*)d_in[10];
    const float* W3    = (const float*)d_in[11];
    const float* b3    = (const float*)d_in[12];
    const float* W4    = (const float*)d_in[13];
    const float* b4    = (const float*)d_in[14];
    const float* W5    = (const float*)d_in[15];
    const float* b5    = (const float*)d_in[16];
    const float* W6    = (const float*)d_in[17];
    const float* b6    = (const float*)d_in[18];

    int T = in_sizes[2] / D_BB;

    static int cfg = 0;
    if (!cfg) {
        cudaFuncSetAttribute(critic_mma,
                             cudaFuncAttributeMaxDynamicSharedMemorySize,
                             SMEM_TOTAL);
        cfg = 1;
    }

    prep_B<<<120, 256>>>(W1);
    critic_mma<<<(T + 31) / 32, 512, SMEM_TOTAL>>>(
        bb, res, fr, estep, enode, ccl, cnd,
        b1, W3, b3, W4, b4, W5, b5, W6, b6, (float*)d_out, T);
}

// round 7
// speedup vs baseline: 3.0055x; 1.0770x over previous
#include <cuda_runtime.h>
#include <cuda_bf16.h>
#include <math.h>
#include <stdint.h>

#define D_BB 768
#define KPAD 960          // 160 feat(+pad) + 768 bb + 32 pad
#define CH   64           // k per chunk
#define NCH  15           // chunks
#define NSTG 4            // smem pipeline stages
#define BUFB 40960        // bytes per stage: Ah 4K | Al 4K | Bh 16K | Bl 16K
#define SMEM_TOTAL (NSTG * BUFB)

typedef unsigned long long u64;
typedef unsigned int       u32;

// ---- W1 pre-split to bf16 hi/lo, transposed [n][k] --------------------------
__device__ __align__(16) __nv_bfloat16 g_Bh[128 * KPAD];
__device__ __align__(16) __nv_bfloat16 g_Bl[128 * KPAD];

// ---- helpers -----------------------------------------------------------------
__device__ __forceinline__ u32 smem_u32(const void* p) {
    u32 a;
    asm("{ .reg .u64 t; cvta.to.shared.u64 t, %1; cvt.u32.u64 %0, t; }"
        : "=r"(a) : "l"(p));
    return a;
}
__device__ __forceinline__ u32 SWZ(u32 b) { return b ^ ((b >> 3) & 0x70); }

__device__ __forceinline__ u32 pack_bf2(float lo, float hi) {
    __nv_bfloat162 v = __floats2bfloat162_rn(lo, hi);
    return *(u32*)&v;
}
__device__ __forceinline__ float bfr(float x) {
    return __bfloat162float(__float2bfloat16_rn(x));
}

#define LDMX4(r, addr) \
    asm volatile("ldmatrix.sync.aligned.m8n8.x4.shared.b16 {%0,%1,%2,%3}, [%4];" \
        : "=r"((r)[0]), "=r"((r)[1]), "=r"((r)[2]), "=r"((r)[3]) : "r"(addr))

#define MMA16816(d, a, b0, b1) \
    asm volatile("mma.sync.aligned.m16n8k16.row.col.f32.bf16.bf16.f32 " \
        "{%0,%1,%2,%3}, {%4,%5,%6,%7}, {%8,%9}, {%0,%1,%2,%3};" \
        : "+f"((d)[0]), "+f"((d)[1]), "+f"((d)[2]), "+f"((d)[3]) \
        : "r"((a)[0]), "r"((a)[1]), "r"((a)[2]), "r"((a)[3]), "r"(b0), "r"(b1))

#define CPA16(dst, src) \
    asm volatile("cp.async.cg.shared.global [%0], [%1], 16;" \
        :: "r"(dst), "l"(src) : "memory")
#define CPA_COMMIT() asm volatile("cp.async.commit_group;" ::: "memory")
#define CPA_WAIT(n)  asm volatile("cp.async.wait_group %0;" :: "n"(n) : "memory")

#define STS64(r0, r1, sa) \
    asm volatile("st.shared.v2.b32 [%0], {%1, %2};" \
        :: "r"(sa), "r"(r0), "r"(r1) : "memory")

// -----------------------------------------------------------------------------
// Prep: W1 [918,128] fp32 -> g_Bh/g_Bl [128 n][960 k] bf16 split (row remap).
// -----------------------------------------------------------------------------
__global__ void prep_B(const float* __restrict__ W1) {
    int id = blockIdx.x * 256 + threadIdx.x;        // 128 n * 240 groups of 4
    if (id >= 128 * 240) return;
    int n  = id / 240;
    int k4 = (id % 240) * 4;
    u32 hw[2], lw[2];
    #pragma unroll
    for (int p = 0; p < 2; p++) {
        float v0 = 0.f, v1 = 0.f;
        int g0 = k4 + p * 2, g1 = g0 + 1;
        if (g0 < 150)                    v0 = W1[(size_t)g0 * 128 + n];
        else if (g0 >= 160 && g0 < 928)  v0 = W1[(size_t)(g0 - 10) * 128 + n];
        if (g1 < 150)                    v1 = W1[(size_t)g1 * 128 + n];
        else if (g1 >= 160 && g1 < 928)  v1 = W1[(size_t)(g1 - 10) * 128 + n];
        float h0 = bfr(v0), h1 = bfr(v1);
        hw[p] = pack_bf2(v0, v1);
        lw[p] = pack_bf2(v0 - h0, v1 - h1);
    }
    *(u64*)&g_Bh[(size_t)n * KPAD + k4] = (u64)hw[0] | ((u64)hw[1] << 32);
    *(u64*)&g_Bl[(size_t)n * KPAD + k4] = (u64)lw[0] | ((u64)lw[1] << 32);
}

// -----------------------------------------------------------------------------
// Fused kernel: grid = T/32 CTAs, 512 threads (16 warps: 2 M x 8 N tiles).
// 4-stage pipeline, A register-prefetched one chunk ahead of its STS.
// -----------------------------------------------------------------------------
__global__ void __launch_bounds__(512)
critic_mma(const float* __restrict__ bb,
           const float* __restrict__ res,   const float* __restrict__ fr,
           const float* __restrict__ estep, const float* __restrict__ enode,
           const float* __restrict__ ccl,   const float* __restrict__ cnd,
           const float* __restrict__ b1,
           const float* __restrict__ W3, const float* __restrict__ b3,
           const float* __restrict__ W4, const float* __restrict__ b4,
           const float* __restrict__ W5, const float* __restrict__ b5,
           const float* __restrict__ W6, const float* __restrict__ b6,
           float* __restrict__ out, int T)
{
    extern __shared__ __align__(16) char dsm[];
    const u32 sb = smem_u32(dsm);

    const int tid  = threadIdx.x;
    const int lane = tid & 31;
    const int wid  = tid >> 5;
    const int mbase = blockIdx.x * 32;

    const int m0w = (wid & 1) * 16;
    const int n0w = (wid >> 1) * 16;

    // ---- A loader mapping: thread -> (row, 4 consecutive k) ----
    const int ar = tid >> 4;                // 0..31
    const int ak = (tid & 15) * 4;          // 0..60
    int atask = mbase + ar; if (atask >= T) atask = T - 1;
    const float* bbrow = bb + (size_t)atask * D_BB;
    const u32 aoff = SWZ((u32)(ar * 128 + ak * 2));

    // ---- B loader mapping: 2 x (row, 16B seg) per thread per buffer ----
    int brow[2], bseg[2]; u32 bdst[2];
    #pragma unroll
    for (int i = 0; i < 2; i++) {
        int id = tid + i * 512;
        brow[i] = id >> 3;
        bseg[i] = id & 7;
        bdst[i] = SWZ((u32)(brow[i] * 128 + bseg[i] * 16));
    }

    // ---- fragment address bases ----
    const u32 aRowByte = (u32)((m0w + (lane & 7) + ((lane >> 3) & 1) * 8) * 128
                               + (lane >> 4) * 16);
    const u32 bRowByte = (u32)((n0w + (lane >> 4) * 8 + (lane & 7)) * 128
                               + ((lane >> 3) & 1) * 16);

    float Da[2][4], Db[2][4], Dc[2][4];
    #pragma unroll
    for (int h = 0; h < 2; h++)
        #pragma unroll
        for (int j = 0; j < 4; j++) { Da[h][j] = 0.f; Db[h][j] = 0.f; Dc[h][j] = 0.f; }

    // generic A fetch (features / backbone / pad) -> 4 floats
    auto loadA_gen = [&](int c, float* x) {
        int g0 = c * CH + ak;
        if (g0 >= 160 && g0 + 4 <= 928) {
            float4 v = *(const float4*)(bbrow + (g0 - 160));
            x[0] = v.x; x[1] = v.y; x[2] = v.z; x[3] = v.w;
        } else {
            #pragma unroll
            for (int j = 0; j < 4; j++) {
                int gk = g0 + j;
                float v = 0.f;
                if (gk < 150) {
                    int nn = gk / 30, rem = gk - nn * 30;
                    int mm = rem / 6, oo = rem - mm * 6;
                    v = res[atask * 5 + nn] * fr[atask * 5 + mm] * estep[atask * 6 + oo];
                } else if (gk >= 160 && gk < 928) {
                    v = bbrow[gk - 160];
                }
                x[j] = v;
            }
        }
    };
    // steady-state A fetch: pure backbone or zero-pad tail
    auto loadA_bb = [&](int c, float* x) {
        int g0 = c * CH + ak;
        if (g0 + 4 <= 928) {
            float4 v = *(const float4*)(bbrow + (g0 - 160));
            x[0] = v.x; x[1] = v.y; x[2] = v.z; x[3] = v.w;
        } else {
            x[0] = x[1] = x[2] = x[3] = 0.f;
        }
    };
    auto storeA = [&](int c, const float* x) {
        const u32 base = sb + (u32)(c % NSTG) * BUFB;
        float h0 = bfr(x[0]), h1 = bfr(x[1]), h2 = bfr(x[2]), h3 = bfr(x[3]);
        STS64(pack_bf2(x[0], x[1]), pack_bf2(x[2], x[3]), base + aoff);
        STS64(pack_bf2(x[0] - h0, x[1] - h1), pack_bf2(x[2] - h2, x[3] - h3),
              base + 4096 + aoff);
    };
    auto issueB = [&](int c) {
        const u32 base = sb + (u32)(c % NSTG) * BUFB;
        #pragma unroll
        for (int i = 0; i < 2; i++) {
            const size_t so = (size_t)brow[i] * KPAD + c * CH + bseg[i] * 8;
            CPA16(base + 8192  + bdst[i], g_Bh + so);
            CPA16(base + 24576 + bdst[i], g_Bl + so);
        }
    };
    auto compute = [&](int c) {
        const u32 base = sb + (u32)(c % NSTG) * BUFB;
        const u32 sAh = base, sAl = base + 4096, sBh = base + 8192, sBl = base + 24576;
        #pragma unroll
        for (int ks = 0; ks < 4; ks++) {
            const u32 ao = SWZ(aRowByte + ks * 32);
            const u32 bo = SWZ(bRowByte + ks * 32);
            u32 a_h[4], a_l[4], b_h[4], b_l[4];
            LDMX4(a_h, sAh + ao);
            LDMX4(b_h, sBh + bo);
            LDMX4(a_l, sAl + ao);
            LDMX4(b_l, sBl + bo);
            MMA16816(Da[0], a_h, b_h[0], b_h[1]);
            MMA16816(Db[0], a_h, b_l[0], b_l[1]);
            MMA16816(Dc[0], a_l, b_h[0], b_h[1]);
            MMA16816(Da[1], a_h, b_h[2], b_h[3]);
            MMA16816(Db[1], a_h, b_l[2], b_l[3]);
            MMA16816(Dc[1], a_l, b_h[2], b_h[3]);
        }
    };

    // ---- prologue: fill stages 0..2, prefetch A(3) into regs ----
    float xp0[4], xp1[4], xp2[4];
    loadA_gen(0, xp0); loadA_gen(1, xp1); loadA_gen(2, xp2);
    storeA(0, xp0); issueB(0); CPA_COMMIT();
    storeA(1, xp1); issueB(1); CPA_COMMIT();
    storeA(2, xp2); issueB(2); CPA_COMMIT();
    float xcur[4];
    loadA_bb(3, xcur);
    CPA_WAIT(2);            // stage 0 B complete
    __syncthreads();

    // ---- main loop: 1 sync/chunk; A staged from regs; LDG 1 chunk ahead ----
    for (int c = 0; c < NCH; c++) {
        compute(c);
        if (c + 3 < NCH) {
            storeA(c + 3, xcur);       // regs loaded at iteration c-1
            if (c + 4 < NCH) loadA_bb(c + 4, xcur);
            issueB(c + 3); CPA_COMMIT();
            CPA_WAIT(2);               // stage c+1 complete
        } else if (c + 2 < NCH) {
            CPA_WAIT(1);
        } else if (c + 1 < NCH) {
            CPA_WAIT(0);
        }
        __syncthreads();
    }

    // ---- combine accumulator sets, stage to smem ----
    float* hsm = (float*)dsm;               // [32][132]
    const int drow = m0w + (lane >> 2);
    #pragma unroll
    for (int h = 0; h < 2; h++) {
        int col = n0w + h * 8 + 2 * (lane & 3);
        float d0 = Da[h][0] + Db[h][0] + Dc[h][0];
        float d1 = Da[h][1] + Db[h][1] + Dc[h][1];
        float d2 = Da[h][2] + Db[h][2] + Dc[h][2];
        float d3 = Da[h][3] + Db[h][3] + Dc[h][3];
        *(float2*)&hsm[drow * 132 + col]       = make_float2(d0, d1);
        *(float2*)&hsm[(drow + 8) * 132 + col] = make_float2(d2, d3);
    }
    __syncthreads();

    // ---- per-task epilogue: 16 warps x 2 tasks ----
    const int n0 = lane * 4;
    const float4 bj = *(const float4*)&b1[n0];
    const float4 w3 = *(const float4*)&W3[n0];
    const float4 w4 = *(const float4*)&W4[n0];
    const float4 w5 = *(const float4*)&W5[n0];
    const float4 w6 = *(const float4*)&W6[n0];
    const float B3 = b3[0], B4 = b4[0], B5 = b5[0], B6 = b6[0];

    #pragma unroll
    for (int it = 0; it < 2; it++) {
        int m = wid * 2 + it;
        int task = mbase + m;
        bool ok = (task < T);
        int rt = ok ? task : (T - 1);

        float4 s = *(const float4*)&hsm[m * 132 + n0];
        float h0 = fmaxf(s.x + bj.x, 0.f), h1 = fmaxf(s.y + bj.y, 0.f);
        float h2 = fmaxf(s.z + bj.z, 0.f), h3 = fmaxf(s.w + bj.w, 0.f);
        float p3 = h0*w3.x + h1*w3.y + h2*w3.z + h3*w3.w;
        float p4 = h0*w4.x + h1*w4.y + h2*w4.z + h3*w4.w;
        float p5 = h0*w5.x + h1*w5.y + h2*w5.z + h3*w5.w;
        float p6 = h0*w6.x + h1*w6.y + h2*w6.z + h3*w6.w;

        float se = enode[(size_t)rt * 64 + lane] + enode[(size_t)rt * 64 + lane + 32];
        float sc = (lane < 4) ? ccl[rt * 4 + lane] : 0.0f;
        float sn = cnd[(size_t)rt * 32 + lane];

        #pragma unroll
        for (int off = 16; off; off >>= 1) {
            p3 += __shfl_xor_sync(0xffffffffu, p3, off);
            p4 += __shfl_xor_sync(0xffffffffu, p4, off);
            p5 += __shfl_xor_sync(0xffffffffu, p5, off);
            p6 += __shfl_xor_sync(0xffffffffu, p6, off);
            se += __shfl_xor_sync(0xffffffffu, se, off);
            sc += __shfl_xor_sync(0xffffffffu, sc, off);
            sn += __shfl_xor_sync(0xffffffffu, sn, off);
        }
        if (lane == 0 && ok) {
            float me = se * (1.0f / 64.0f);
            float ss = sc * sn;
            float y51 = 1.0f / (1.0f + expf(-(p3 * me + B3)));
            float y61 = p4 * me + B4;
            float y52 = 1.0f / (1.0f + expf(-(p5 * ss + B5)));
            float y62 = p6 * ss + B6;
            float p = y51 * y52;
            out[task] = (1.0f - p) * (-100.0f) + p * (y61 + y62);
        }
    }
}

// -----------------------------------------------------------------------------
extern "C" void kernel_launch(void* const* d_in, const int* in_sizes, int n_in,
                              void* d_out, int out_size) {
    const float* bb    = (const float*)d_in[2];
    const float* res   = (const float*)d_in[3];
    const float* fr    = (const float*)d_in[4];
    const float* estep = (const float*)d_in[5];
    const float* enode = (const float*)d_in[6];
    const float* ccl   = (const float*)d_in[7];
    const float* cnd   = (const float*)d_in[8];
    const float* W1    = (const float*)d_in[9];
    const float* b1    = (const float*)d_in[10];
    const float* W3    = (const float*)d_in[11];
    const float* b3    = (const float*)d_in[12];
    const float* W4    = (const float*)d_in[13];
    const float* b4    = (const float*)d_in[14];
    const float* W5    = (const float*)d_in[15];
    const float* b5    = (const float*)d_in[16];
    const float* W6    = (const float*)d_in[17];
    const float* b6    = (const float*)d_in[18];

    int T = in_sizes[2] / D_BB;

    static int cfg = 0;
    if (!cfg) {
        cudaFuncSetAttribute(critic_mma,
                             cudaFuncAttributeMaxDynamicSharedMemorySize,
                             SMEM_TOTAL);
        cfg = 1;
    }

    prep_B<<<120, 256>>>(W1);
    critic_mma<<<(T + 31) / 32, 512, SMEM_TOTAL>>>(
        bb, res, fr, estep, enode, ccl, cnd,
        b1, W3, b3, W4, b4, W5, b5, W6, b6, (float*)d_out, T);
}